// round 4
// baseline (speedup 1.0000x reference)
#include <cuda_runtime.h>
#include <stdint.h>

// ===========================================================================
// RLMoERouter — fused single-launch version.
// Reproduces jax.random.categorical(key(42), prefs/T, (4,8192,2)) bit-exactly
// via Threefry-2x32 (jax_threefry_partitionable=True, out = o0 ^ o1), then the
// REINFORCE count/std/prefs update — all in ONE kernel using the
// last-block-ticket pattern. Device state (d_counts, d_done) is reset by the
// finalizing block, so every graph replay is deterministic.
// ===========================================================================

#define NUM_EXPERTS 64
#define NDRAWS      65536          // 4 * 8192 * 2
#define THREADS     256            // 8 warps/block, 1 warp per draw
#define WARPS_PER_BLOCK (THREADS / 32)
#define GRID        (NDRAWS / WARPS_PER_BLOCK)   // 8192 blocks

__device__ int          d_counts[NUM_EXPERTS];   // zero-init; reset by last block
__device__ unsigned int d_done = 0;              // ticket;   reset by last block

// jax.random.key(42) -> threefry key pair (0, 42)
__device__ __forceinline__ uint2 threefry2x32(uint32_t x0, uint32_t x1) {
    const uint32_t ks0 = 0u;
    const uint32_t ks1 = 42u;
    const uint32_t ks2 = 0x1BD11BDAu ^ ks0 ^ ks1;
    x0 += ks0; x1 += ks1;
#define TF_R(r) { x0 += x1; x1 = __funnelshift_l(x1, x1, (r)); x1 ^= x0; }
    TF_R(13) TF_R(15) TF_R(26) TF_R(6)
    x0 += ks1; x1 += ks2 + 1u;
    TF_R(17) TF_R(29) TF_R(16) TF_R(24)
    x0 += ks2; x1 += ks0 + 2u;
    TF_R(13) TF_R(15) TF_R(26) TF_R(6)
    x0 += ks0; x1 += ks1 + 3u;
    TF_R(17) TF_R(29) TF_R(16) TF_R(24)
    x0 += ks1; x1 += ks2 + 4u;
    TF_R(13) TF_R(15) TF_R(26) TF_R(6)
    x0 += ks2; x1 += ks0 + 5u;
#undef TF_R
    return make_uint2(x0, x1);
}

// Warp-wide argmax on uint32 keys, ties -> lowest index (matches jnp.argmax).
__device__ __forceinline__ void warp_argmax(uint32_t& key, int& idx) {
#pragma unroll
    for (int off = 16; off; off >>= 1) {
        uint32_t ok = __shfl_xor_sync(0xffffffffu, key, off);
        int      oi = __shfl_xor_sync(0xffffffffu, idx, off);
        if (ok > key || (ok == key && oi < idx)) { key = ok; idx = oi; }
    }
}

__global__ void __launch_bounds__(THREADS)
fused_kernel(const float* __restrict__ prefs, float* __restrict__ out) {
    __shared__ float s_l[NUM_EXPERTS];     // logits
    __shared__ float s_tmp[NUM_EXPERTS];   // exp / scratch
    __shared__ float s_probs[NUM_EXPERTS];
    __shared__ int   s_uni;
    __shared__ int   s_last;

    const int tid  = threadIdx.x;
    const int lane = tid & 31;

    // ---- per-block softmax setup (replaces setup_kernel) ----
    if (tid < NUM_EXPERTS) s_l[tid] = prefs[tid];   // TEMPERATURE = 1.0
    __syncthreads();
    if (tid < NUM_EXPERTS) {
        float mx = -3.402823466e+38f, mn = 3.402823466e+38f;
#pragma unroll 8
        for (int i = 0; i < NUM_EXPERTS; i++) { mx = fmaxf(mx, s_l[i]); mn = fminf(mn, s_l[i]); }
        s_tmp[tid] = expf(s_l[tid] - mx);
        if (tid == 0) s_uni = (mx == mn) ? 1 : 0;
    }
    __syncthreads();
    if (tid < NUM_EXPERTS) {
        float s = 0.0f;
#pragma unroll 8
        for (int i = 0; i < NUM_EXPERTS; i++) s += s_tmp[i];
        s_probs[tid] = s_tmp[tid] / s;   // exactly 1/64 for zero prefs
    }
    __syncthreads();

    const int uni = s_uni;

    // ---- sampling: one warp per draw, 2 experts per lane ----
    const int d  = blockIdx.x * WARPS_PER_BLOCK + (tid >> 5);
    const int c0 = lane, c1 = lane + 32;
    const uint32_t j0 = (uint32_t)d * 64u + (uint32_t)c0;   // flat elem index, hi=0
    uint2 r0 = threefry2x32(0u, j0);
    uint2 r1 = threefry2x32(0u, j0 + 32u);
    uint32_t b0 = r0.x ^ r0.y;
    uint32_t b1 = r1.x ^ r1.y;

    uint32_t key, k2;
    int idx;
    if (uni) {
        // Uniform logits: gumbel(u) strictly increasing & injective in (bits>>9)
        // on the 2^23 grid, so mantissa bits are a faithful ranking key
        // INCLUDING first-index tie-breaking.
        key = b0 >> 9; k2 = b1 >> 9;
    } else {
        // General path (never taken for this input: prefs == 0).
        const float tiny = 1.17549435082228751e-38f;
        float u0 = fmaxf(tiny, (__uint_as_float((b0 >> 9) | 0x3f800000u) - 1.0f) * (1.0f - tiny) + tiny);
        float u1 = fmaxf(tiny, (__uint_as_float((b1 >> 9) | 0x3f800000u) - 1.0f) * (1.0f - tiny) + tiny);
        float sc0 = s_l[c0] - logf(-logf(u0));
        float sc1 = s_l[c1] - logf(-logf(u1));
        uint32_t su0 = __float_as_uint(sc0), su1 = __float_as_uint(sc1);
        key = (su0 & 0x80000000u) ? ~su0 : (su0 | 0x80000000u);
        k2  = (su1 & 0x80000000u) ? ~su1 : (su1 | 0x80000000u);
    }
    idx = c0;
    if (k2 > key) { key = k2; idx = c1; }
    warp_argmax(key, idx);

    if (lane == 0) {
        out[d]          = (float)idx;
        out[NDRAWS + d] = s_probs[idx];
        atomicAdd(&d_counts[idx], 1);
        __threadfence();             // order our count before our ticket
    }
    __syncthreads();

    // ---- last-block ticket -> finalize (replaces finalize_kernel) ----
    if (tid == 0) {
        unsigned int t = atomicAdd(&d_done, 1u);
        s_last = (t == (unsigned int)(gridDim.x - 1)) ? 1 : 0;
    }
    __syncthreads();

    if (s_last) {
        if (tid < NUM_EXPERTS) {
            float c = (float)__ldcg(&d_counts[tid]);
            s_tmp[tid] = c;
        }
        __syncthreads();
        if (tid < NUM_EXPERTS) {
            float sum = 0.0f;
#pragma unroll 8
            for (int i = 0; i < NUM_EXPERTS; i++) sum += s_tmp[i];
            float mean = sum * (1.0f / NUM_EXPERTS);
            float dev  = s_tmp[tid] - mean;
            s_l[tid] = dev * dev;               // reuse smem as scratch
        }
        __syncthreads();
        if (tid < NUM_EXPERTS) {
            float ss = 0.0f;
#pragma unroll 8
            for (int i = 0; i < NUM_EXPERTS; i++) ss += s_l[i];
            float sum  = 0.0f;
#pragma unroll 8
            for (int i = 0; i < NUM_EXPERTS; i++) sum += s_tmp[i];
            float mean   = sum * (1.0f / NUM_EXPERTS);
            float stdv   = sqrtf(ss / (float)(NUM_EXPERTS - 1));  // ddof=1
            float reward = -(stdv / mean);
            float adv    = reward;                                // baseline = 0
            float freq   = s_tmp[tid] / sum;
            out[2 * NDRAWS + tid] = prefs[tid] + 0.1f * adv * (freq - s_probs[tid]);
            if (tid == 0) out[2 * NDRAWS + NUM_EXPERTS] = 0.1f * adv;  // new_baseline

            // reset device state for the next (graph-replayed) call
            d_counts[tid] = 0;
            if (tid == 0) d_done = 0u;
        }
    }
}

extern "C" void kernel_launch(void* const* d_in, const int* in_sizes, int n_in,
                              void* d_out, int out_size) {
    (void)out_size;
    // inputs: x (unused, 67108864 elems), prefs (64 elems) — pick by size.
    const float* prefs = nullptr;
    for (int i = 0; i < n_in; i++)
        if (in_sizes[i] == NUM_EXPERTS) prefs = (const float*)d_in[i];
    if (!prefs) prefs = (const float*)d_in[n_in - 1];

    fused_kernel<<<GRID, THREADS>>>(prefs, (float*)d_out);
}

// round 5
// speedup vs baseline: 2.2596x; 2.2596x over previous
#include <cuda_runtime.h>
#include <stdint.h>

// ===========================================================================
// RLMoERouter — fused, thread-per-draw version.
// Reproduces jax.random.categorical(key(42), prefs/T, (4,8192,2)) bit-exactly
// via Threefry-2x32 (jax_threefry_partitionable=True, out = o0 ^ o1).
// One THREAD owns one draw: 64 independent threefry calls, argmax kept as a
// single running umax over packed keys ((mantissa<<6)|(63-c)) — no shuffles,
// no cross-lane traffic, fully coalesced stores. REINFORCE finalize via
// last-block ticket; device state reset each call (graph-replay safe).
// ===========================================================================

#define NUM_EXPERTS 64
#define NDRAWS      65536          // 4 * 8192 * 2
#define THREADS     64             // 1 thread per draw, 2 warps/block
#define GRID        (NDRAWS / THREADS)   // 1024 blocks

__device__ int          d_counts[NUM_EXPERTS];   // zero-init; reset by last block
__device__ unsigned int d_done = 0;              // ticket;   reset by last block

// jax.random.key(42) -> threefry key pair (0, 42)
__device__ __forceinline__ uint2 threefry2x32(uint32_t x0, uint32_t x1) {
    const uint32_t ks0 = 0u;
    const uint32_t ks1 = 42u;
    const uint32_t ks2 = 0x1BD11BDAu ^ ks0 ^ ks1;
    x0 += ks0; x1 += ks1;
#define TF_R(r) { x0 += x1; x1 = __funnelshift_l(x1, x1, (r)); x1 ^= x0; }
    TF_R(13) TF_R(15) TF_R(26) TF_R(6)
    x0 += ks1; x1 += ks2 + 1u;
    TF_R(17) TF_R(29) TF_R(16) TF_R(24)
    x0 += ks2; x1 += ks0 + 2u;
    TF_R(13) TF_R(15) TF_R(26) TF_R(6)
    x0 += ks0; x1 += ks1 + 3u;
    TF_R(17) TF_R(29) TF_R(16) TF_R(24)
    x0 += ks1; x1 += ks2 + 4u;
    TF_R(13) TF_R(15) TF_R(26) TF_R(6)
    x0 += ks2; x1 += ks0 + 5u;
#undef TF_R
    return make_uint2(x0, x1);
}

__global__ void __launch_bounds__(THREADS)
fused_kernel(const float* __restrict__ prefs, float* __restrict__ out) {
    __shared__ float s_l[NUM_EXPERTS];     // logits
    __shared__ float s_tmp[NUM_EXPERTS];   // exp / scratch
    __shared__ float s_probs[NUM_EXPERTS];
    __shared__ int   s_hist[NUM_EXPERTS];
    __shared__ int   s_uni;
    __shared__ int   s_last;

    const int tid = threadIdx.x;           // 0..63 == expert id in setup

    // ---- per-block softmax setup ----
    s_l[tid]    = prefs[tid];              // TEMPERATURE = 1.0
    s_hist[tid] = 0;
    __syncthreads();
    {
        float mx = -3.402823466e+38f, mn = 3.402823466e+38f;
#pragma unroll 8
        for (int i = 0; i < NUM_EXPERTS; i++) { mx = fmaxf(mx, s_l[i]); mn = fminf(mn, s_l[i]); }
        s_tmp[tid] = expf(s_l[tid] - mx);
        if (tid == 0) s_uni = (mx == mn) ? 1 : 0;
    }
    __syncthreads();
    {
        float s = 0.0f;
#pragma unroll 8
        for (int i = 0; i < NUM_EXPERTS; i++) s += s_tmp[i];
        s_probs[tid] = s_tmp[tid] / s;     // exactly 1/64 for zero prefs
    }
    __syncthreads();

    // ---- sampling: one thread per draw, 64 independent threefry calls ----
    const int d = blockIdx.x * THREADS + tid;
    const uint32_t base = (uint32_t)d * 64u;   // flat elem index, counter hi = 0
    int idx;

    if (s_uni) {
        // Uniform logits: gumbel(u) is strictly increasing & injective in
        // (bits>>9) on the 2^23 grid, so the mantissa is a faithful ranking
        // key. Pack (m<<6)|(63-c): ties in m pick larger (63-c) = smaller c
        // = jnp.argmax first-index tie-break. One umax per expert.
        uint32_t best = 0u;
#pragma unroll 8
        for (uint32_t c = 0; c < NUM_EXPERTS; c++) {
            uint2 r = threefry2x32(0u, base + c);
            uint32_t m = (r.x ^ r.y) >> 9;
            uint32_t p = (m << 6) | (63u - c);
            best = (p > best) ? p : best;
        }
        idx = 63 - (int)(best & 63u);
    } else {
        // General path (never taken for this input: prefs == 0):
        // replicate jax.random.uniform(tiny,1) -> gumbel -> +logits scoring.
        uint32_t key = 0u;
        idx = 0;
        const float tiny = 1.17549435082228751e-38f;
        for (int c = 0; c < NUM_EXPERTS; c++) {
            uint2 r = threefry2x32(0u, base + (uint32_t)c);
            uint32_t m = (r.x ^ r.y) >> 9;
            float uf = __uint_as_float(m | 0x3f800000u) - 1.0f;
            float u  = fmaxf(tiny, uf * (1.0f - tiny) + tiny);
            float sc = s_l[c] - logf(-logf(u));
            uint32_t su = __float_as_uint(sc);
            uint32_t k  = (su & 0x80000000u) ? ~su : (su | 0x80000000u);
            if (c == 0 || k > key) { key = k; idx = c; }
        }
    }

    out[d]          = (float)idx;          // coalesced
    out[NDRAWS + d] = s_probs[idx];        // coalesced store, LDS gather
    atomicAdd(&s_hist[idx], 1);
    __syncthreads();

    // ---- flush block histogram, then last-block ticket -> finalize ----
    int h = s_hist[tid];
    if (h) atomicAdd(&d_counts[tid], h);
    __threadfence();
    __syncthreads();

    if (tid == 0) {
        unsigned int t = atomicAdd(&d_done, 1u);
        s_last = (t == (unsigned int)(GRID - 1)) ? 1 : 0;
    }
    __syncthreads();

    if (s_last) {
        float c = (float)__ldcg(&d_counts[tid]);
        s_tmp[tid] = c;
        __syncthreads();
        float sum = 0.0f;
#pragma unroll 8
        for (int i = 0; i < NUM_EXPERTS; i++) sum += s_tmp[i];
        float mean = sum * (1.0f / NUM_EXPERTS);
        float dev  = c - mean;
        s_l[tid] = dev * dev;
        __syncthreads();
        float ss = 0.0f;
#pragma unroll 8
        for (int i = 0; i < NUM_EXPERTS; i++) ss += s_l[i];
        float stdv   = sqrtf(ss / (float)(NUM_EXPERTS - 1));   // ddof=1
        float reward = -(stdv / mean);
        float adv    = reward;                                  // baseline = 0
        float freq   = c / sum;
        out[2 * NDRAWS + tid] = prefs[tid] + 0.1f * adv * (freq - s_probs[tid]);
        if (tid == 0) out[2 * NDRAWS + NUM_EXPERTS] = 0.1f * adv;  // new_baseline

        // reset device state for the next (graph-replayed) call
        d_counts[tid] = 0;
        if (tid == 0) d_done = 0u;
    }
}

extern "C" void kernel_launch(void* const* d_in, const int* in_sizes, int n_in,
                              void* d_out, int out_size) {
    (void)out_size;
    // inputs: x (unused, 67108864 elems), prefs (64 elems) — pick by size.
    const float* prefs = nullptr;
    for (int i = 0; i < n_in; i++)
        if (in_sizes[i] == NUM_EXPERTS) prefs = (const float*)d_in[i];
    if (!prefs) prefs = (const float*)d_in[n_in - 1];

    fused_kernel<<<GRID, THREADS>>>(prefs, (float*)d_out);
}